// round 2
// baseline (speedup 1.0000x reference)
#include <cuda_runtime.h>

// LiftSplatShoot voxel pooling via counting-sort + atomic-free gather.
// out[c * 40000 + gx*200 + gy] = sum over points in voxel (gx,gy) of x[p][c].

#define NX0   200
#define NX1   200
#define NVOX  (NX0 * NX1)
#define NCH   32
#define MAXP  2800000              // actual nprime = 2,770,944
#define SCAN_BLK 256
#define NBLK  ((NVOX + SCAN_BLK - 1) / SCAN_BLK)   // 157

static __device__ unsigned short g_vox[MAXP];      // voxel id per point (0xFFFF = dropped)
static __device__ int g_pidx[MAXP];                // point indices sorted by voxel
static __device__ int g_count[NVOX];
static __device__ int g_offset[NVOX + 1];
static __device__ int g_cursor[NVOX];
static __device__ int g_bsum[SCAN_BLK];
static __device__ int g_blockoff[SCAN_BLK];

// ---------- K1: zero histogram counters ----------
__global__ void k_zero() {
    int t = blockIdx.x * blockDim.x + threadIdx.x;
    if (t < NVOX) g_count[t] = 0;
}

// ---------- K2: voxel id + histogram ----------
__global__ void k_hist(const float* __restrict__ geom, int n) {
    int p = blockIdx.x * blockDim.x + threadIdx.x;
    if (p >= n) return;
    float px = geom[p * 3 + 0];
    float py = geom[p * 3 + 1];
    float pz = geom[p * 3 + 2];
    // exact match to reference: IEEE add + div, truncate-toward-zero cast
    int gx = (int)__fdiv_rn(__fadd_rn(px, 50.0f), 0.5f);
    int gy = (int)__fdiv_rn(__fadd_rn(py, 50.0f), 0.5f);
    int gz = (int)__fdiv_rn(__fadd_rn(pz, 10.0f), 20.0f);
    unsigned short vox = 0xFFFFu;
    if ((unsigned)gx < NX0 && (unsigned)gy < NX1 && gz == 0) {
        int v = gx * NX1 + gy;
        vox = (unsigned short)v;
        atomicAdd(&g_count[v], 1);     // no return use -> REDG
    }
    g_vox[p] = vox;
}

// ---------- K3a: per-block sums of counts ----------
__global__ void k_blocksum() {
    __shared__ int s[SCAN_BLK];
    int i = blockIdx.x * SCAN_BLK + threadIdx.x;
    s[threadIdx.x] = (i < NVOX) ? g_count[i] : 0;
    __syncthreads();
    for (int off = SCAN_BLK / 2; off > 0; off >>= 1) {
        if (threadIdx.x < off) s[threadIdx.x] += s[threadIdx.x + off];
        __syncthreads();
    }
    if (threadIdx.x == 0) g_bsum[blockIdx.x] = s[0];
}

// ---------- K3b: exclusive scan of block sums ----------
__global__ void k_scanblocks() {
    __shared__ int s[SCAN_BLK];
    int t = threadIdx.x;
    s[t] = (t < NBLK) ? g_bsum[t] : 0;
    __syncthreads();
    for (int off = 1; off < SCAN_BLK; off <<= 1) {
        int u = (t >= off) ? s[t - off] : 0;
        __syncthreads();
        s[t] += u;
        __syncthreads();
    }
    if (t < NBLK) g_blockoff[t] = (t ? s[t - 1] : 0);
    if (t == SCAN_BLK - 1) g_offset[NVOX] = s[SCAN_BLK - 1];   // total kept
}

// ---------- K3c: final offsets + cursors ----------
__global__ void k_scanfinal() {
    __shared__ int s[SCAN_BLK];
    int t = threadIdx.x;
    int i = blockIdx.x * SCAN_BLK + t;
    int v = (i < NVOX) ? g_count[i] : 0;
    s[t] = v;
    __syncthreads();
    for (int off = 1; off < SCAN_BLK; off <<= 1) {
        int u = (t >= off) ? s[t - off] : 0;
        __syncthreads();
        s[t] += u;
        __syncthreads();
    }
    if (i < NVOX) {
        int excl = (t ? s[t - 1] : 0) + g_blockoff[blockIdx.x];
        g_offset[i] = excl;
        g_cursor[i] = excl;
    }
}

// ---------- K4: place point indices into voxel segments ----------
__global__ void k_place(int n) {
    int p = blockIdx.x * blockDim.x + threadIdx.x;
    if (p >= n) return;
    unsigned v = g_vox[p];
    if (v != 0xFFFFu) {
        int slot = atomicAdd(&g_cursor[v], 1);
        g_pidx[slot] = p;
    }
}

// ---------- K5: gather-sum per voxel, atomic-free ----------
// Warp = one voxel. lane = (point-slot [0..3]) * 8 + (channel group [0..7]).
// Each iteration: 4 points; each point's 128B x-row is read fully coalesced
// by its 8 group-lanes. shfl-reduce across point-slots, stage in smem tile,
// write out coalesced (32 consecutive voxels per channel row).
__global__ void __launch_bounds__(1024) k_gather(const float4* __restrict__ xv,
                                                 float* __restrict__ out) {
    __shared__ float tile[32][33];
    int w    = threadIdx.x >> 5;        // warp = voxel within block
    int lane = threadIdx.x & 31;
    int vox  = blockIdx.x * 32 + w;
    int start = g_offset[vox];
    int end   = g_offset[vox + 1];
    int q  = lane & 7;                  // channel group
    int ps = lane >> 3;                 // point slot

    float4 acc = make_float4(0.f, 0.f, 0.f, 0.f);
    for (int s = start + ps; s < end; s += 4) {
        int p = __ldg(&g_pidx[s]);      // 8 lanes share address -> broadcast
        float4 v = xv[p * 8 + q];       // 8 lanes -> one 128B line
        acc.x += v.x; acc.y += v.y; acc.z += v.z; acc.w += v.w;
    }
    // reduce across the 4 point-slots (lanes q, q+8, q+16, q+24)
    #pragma unroll
    for (int off = 8; off <= 16; off <<= 1) {
        acc.x += __shfl_xor_sync(0xFFFFFFFFu, acc.x, off);
        acc.y += __shfl_xor_sync(0xFFFFFFFFu, acc.y, off);
        acc.z += __shfl_xor_sync(0xFFFFFFFFu, acc.z, off);
        acc.w += __shfl_xor_sync(0xFFFFFFFFu, acc.w, off);
    }
    if (lane < 8) {                     // ps == 0 lanes hold the group sums
        tile[w][lane * 4 + 0] = acc.x;
        tile[w][lane * 4 + 1] = acc.y;
        tile[w][lane * 4 + 2] = acc.z;
        tile[w][lane * 4 + 3] = acc.w;
    }
    __syncthreads();
    // write phase: thread (c = w, voxoff = lane) -> out[c][vox0 + voxoff]
    out[w * NVOX + blockIdx.x * 32 + lane] = tile[lane][w];
}

extern "C" void kernel_launch(void* const* d_in, const int* in_sizes, int n_in,
                              void* d_out, int out_size) {
    const float* in0 = (const float*)d_in[0];
    const float* in1 = (const float*)d_in[1];
    int s0 = in_sizes[0], s1 = in_sizes[1];

    const float* geom;
    const float* x;
    int xsize;
    if (s0 < s1) { geom = in0; x = in1; xsize = s1; }
    else         { geom = in1; x = in0; xsize = s0; }

    int n = xsize / NCH;                // number of points

    k_zero<<<(NVOX + 255) / 256, 256>>>();
    k_hist<<<(n + 255) / 256, 256>>>(geom, n);
    k_blocksum<<<NBLK, SCAN_BLK>>>();
    k_scanblocks<<<1, SCAN_BLK>>>();
    k_scanfinal<<<NBLK, SCAN_BLK>>>();
    k_place<<<(n + 255) / 256, 256>>>(n);
    k_gather<<<NVOX / 32, 1024>>>(reinterpret_cast<const float4*>(x),
                                  (float*)d_out);
}